// round 13
// baseline (speedup 1.0000x reference)
#include <cuda_runtime.h>
#include <cuda_fp16.h>
#include <cstdint>

#define SEQ 4096
#define DM  1024
#define NH  16
#define HD  64
#define QSCALE 0.1803368801111204f   // 0.125 * log2(e): S comes out in log2 units
#define ONESH2 0x3C003C00u           // half2(1.0, 1.0)

// ---------------- scratch (__device__ globals; no allocs allowed) -----------
__device__ __half g_xh[SEQ*DM];
__device__ __half g_wqh[DM*DM], g_wkh[DM*DM], g_wvh[DM*DM], g_woh[DM*DM];
__device__ __half g_q[SEQ*DM], g_k[SEQ*DM], g_v[SEQ*DM];   // [h][s][64]
__device__ __half g_ao[SEQ*DM];                             // [s][1024]
__device__ int    g_flags[SEQ/128];  // per-q-block completion counters (reset by f2h_all)

// ---------------- PTX helpers ----------------------------------------------
#define SWZ(o) ((uint32_t)(o) ^ (((uint32_t)(o) >> 3) & 0x70u))

__device__ __forceinline__ uint32_t s2u(const void* p) {
    uint32_t a;
    asm("{ .reg .u64 t; cvta.to.shared.u64 t, %1; cvt.u32.u64 %0, t; }"
        : "=r"(a) : "l"(p));
    return a;
}
__device__ __forceinline__ void cpa16(uint32_t s, const void* g) {
    asm volatile("cp.async.cg.shared.global [%0], [%1], 16;" :: "r"(s), "l"(g));
}
#define CPC()  asm volatile("cp.async.commit_group;" ::: "memory")
#define CPW(n) asm volatile("cp.async.wait_group %0;" :: "n"(n) : "memory")

__device__ __forceinline__ void ldsm4(uint32_t* r, uint32_t a) {
    asm volatile("ldmatrix.sync.aligned.m8n8.x4.shared.b16 {%0,%1,%2,%3}, [%4];"
                 : "=r"(r[0]), "=r"(r[1]), "=r"(r[2]), "=r"(r[3]) : "r"(a));
}
__device__ __forceinline__ void ldsm4t(uint32_t* r, uint32_t a) {
    asm volatile("ldmatrix.sync.aligned.m8n8.x4.trans.shared.b16 {%0,%1,%2,%3}, [%4];"
                 : "=r"(r[0]), "=r"(r[1]), "=r"(r[2]), "=r"(r[3]) : "r"(a));
}
__device__ __forceinline__ void mma16816(float* c, const uint32_t* a,
                                         uint32_t b0, uint32_t b1) {
    asm volatile(
        "mma.sync.aligned.m16n8k16.row.col.f32.f16.f16.f32 "
        "{%0,%1,%2,%3},{%4,%5,%6,%7},{%8,%9},{%0,%1,%2,%3};"
        : "+f"(c[0]), "+f"(c[1]), "+f"(c[2]), "+f"(c[3])
        : "r"(a[0]), "r"(a[1]), "r"(a[2]), "r"(a[3]), "r"(b0), "r"(b1));
}
// fp16-accumulator variant: C regs pack {row r: c,c+1} / {row r+8: c,c+1}
__device__ __forceinline__ void mma16816h(uint32_t* c, const uint32_t* a,
                                          uint32_t b0, uint32_t b1) {
    asm volatile(
        "mma.sync.aligned.m16n8k16.row.col.f16.f16.f16.f16 "
        "{%0,%1},{%2,%3,%4,%5},{%6,%7},{%0,%1};"
        : "+r"(c[0]), "+r"(c[1])
        : "r"(a[0]), "r"(a[1]), "r"(a[2]), "r"(a[3]), "r"(b0), "r"(b1));
}
__device__ __forceinline__ uint32_t h2exp2(uint32_t x) {
    uint32_t r;
    asm("ex2.approx.f16x2 %0, %1;" : "=r"(r) : "r"(x));
    return r;
}

// ---------------- fused, vectorized fp32 -> fp16 convert --------------------
__global__ void f2h_all(const float* __restrict__ x,  const float* __restrict__ wq,
                        const float* __restrict__ wk, const float* __restrict__ wv,
                        const float* __restrict__ wo)
{
    if (blockIdx.x == 0 && threadIdx.x < SEQ/128) g_flags[threadIdx.x] = 0;
    const int NX4 = (SEQ * DM) / 4;
    const int NW4 = (DM * DM) / 4;    // 2^18
    const int total = NX4 + 4 * NW4;
    for (int i = blockIdx.x * blockDim.x + threadIdx.x; i < total;
         i += gridDim.x * blockDim.x) {
        const float4* s; __half2* d; int off;
        if (i < NX4) { s = (const float4*)x; d = (__half2*)g_xh; off = i; }
        else {
            const int j = i - NX4, seg = j >> 18;
            off = j & (NW4 - 1);
            if      (seg == 0) { s = (const float4*)wq; d = (__half2*)g_wqh; }
            else if (seg == 1) { s = (const float4*)wk; d = (__half2*)g_wkh; }
            else if (seg == 2) { s = (const float4*)wv; d = (__half2*)g_wvh; }
            else               { s = (const float4*)wo; d = (__half2*)g_woh; }
        }
        const float4 v = s[off];
        d[2 * off]     = __floats2half2_rn(v.x, v.y);
        d[2 * off + 1] = __floats2half2_rn(v.z, v.w);
    }
}

// ---------------- GEMM: CTA 128x128, 4 warps (2x2), warp 64x64 --------------
// BK=64, 3-stage cp.async (.cg), SW128. Frozen mma.sync-floor configuration.
#define GSTG 32768
#define GEMM_SMEM (3 * GSTG)    // 98304

// gemm body shared by the QKV kernel and the fused out-projection path.
template <int IS_OUT>
__device__ __forceinline__ void gemm_body(
    int m0, int n0, int z,
    const float* __restrict__ bqv, const float* __restrict__ bvv,
    float* __restrict__ O32, char* smc)
{
    const uint32_t smb = s2u(smc);
    const int t = threadIdx.x, l = t & 31, wid = t >> 5;
    const int wm = wid >> 1, wn = wid & 1;

    const __half* A = IS_OUT ? g_ao : g_xh;
    const __half* B = IS_OUT ? g_woh
                             : (z == 0) ? g_wqh : (z == 1) ? g_wkh : g_wvh;

    float c[4][8][4];
#pragma unroll
    for (int mt = 0; mt < 4; mt++)
#pragma unroll
        for (int nt = 0; nt < 8; nt++)
#pragma unroll
            for (int j = 0; j < 4; j++) c[mt][nt][j] = 0.f;

    auto issue = [&](int ch) {
        const uint32_t sa = smb + (ch % 3) * GSTG;
#pragma unroll
        for (int i = 0; i < 8; i++) {
            const int idx = t + i * 128, row = idx >> 3, s = idx & 7;
            const size_t ko = (size_t)ch * 64 + s * 8;
            const uint32_t so = SWZ(row * 128 + s * 16);
            cpa16(sa + so,         A + (size_t)(m0 + row) * DM + ko);
            cpa16(sa + 16384 + so, B + (size_t)(n0 + row) * DM + ko);
        }
    };
    issue(0); CPC();
    issue(1); CPC();

    const int ar8  = ((l >> 3) & 1) * 8 + (l & 7);
    const int ak16 = (l >> 4) * 16;
    const int br8  = ((l >> 4) & 1) * 8 + (l & 7);
    const int bk16 = ((l >> 3) & 1) * 16;

    for (int ch = 0; ch < 16; ch++) {
        CPW(1);
        __syncthreads();

        const uint32_t sa = smb + (ch % 3) * GSTG, sb = sa + 16384;
#pragma unroll
        for (int ks = 0; ks < 4; ks++) {
            uint32_t a[4][4], b[4][4];
#pragma unroll
            for (int mt = 0; mt < 4; mt++)
                ldsm4(a[mt], sa + SWZ((wm * 64 + mt * 16 + ar8) * 128 + ks * 32 + ak16));
#pragma unroll
            for (int np = 0; np < 4; np++)
                ldsm4(b[np], sb + SWZ((wn * 64 + np * 16 + br8) * 128 + ks * 32 + bk16));
#pragma unroll
            for (int mt = 0; mt < 4; mt++)
#pragma unroll
                for (int np = 0; np < 4; np++) {
                    mma16816(c[mt][2*np],     a[mt], b[np][0], b[np][1]);
                    mma16816(c[mt][2*np + 1], a[mt], b[np][2], b[np][3]);
                }
            if (ks == 0 && ch + 2 < 16) { issue(ch + 2); CPC(); }
        }
    }

    // epilogue
    const float scale = (!IS_OUT && z == 0) ? QSCALE : 1.f;
    const float* bias = IS_OUT ? bqv : (z == 2) ? bvv : bqv;
    const int hasb = IS_OUT || (z != 1);
#pragma unroll
    for (int mt = 0; mt < 4; mt++) {
        const int r = m0 + wm * 64 + mt * 16 + (l >> 2);
#pragma unroll
        for (int nt = 0; nt < 8; nt++) {
            const int n = n0 + wn * 64 + nt * 8 + (l & 3) * 2;
            const float b0 = hasb ? bias[n] : 0.f;
            const float b1 = hasb ? bias[n + 1] : 0.f;
            if (IS_OUT) {
                *(float2*)(O32 + (size_t)r * DM + n) =
                    make_float2(c[mt][nt][0] + b0, c[mt][nt][1] + b1);
                *(float2*)(O32 + (size_t)(r + 8) * DM + n) =
                    make_float2(c[mt][nt][2] + b0, c[mt][nt][3] + b1);
            } else {
                __half* Oh = (z == 0) ? g_q : (z == 1) ? g_k : g_v;
                const int hh = n >> 6, hd = n & 63;
                *(__half2*)(Oh + ((size_t)hh * SEQ + r) * HD + hd) =
                    __floats2half2_rn((c[mt][nt][0] + b0) * scale,
                                      (c[mt][nt][1] + b1) * scale);
                *(__half2*)(Oh + ((size_t)hh * SEQ + r + 8) * HD + hd) =
                    __floats2half2_rn((c[mt][nt][2] + b0) * scale,
                                      (c[mt][nt][3] + b1) * scale);
            }
        }
    }
}

__global__ __launch_bounds__(128, 2) void gemm_qkv(
    const float* __restrict__ bqv, const float* __restrict__ bvv)
{
    extern __shared__ char smc[];
    gemm_body<0>(blockIdx.y * 128, blockIdx.x * 128, blockIdx.z, bqv, bvv,
                 nullptr, smc);
}

// ---------------- attention body: exact R9 champion (frozen) ----------------
#define ASTG 16384
#define ATTN_SMEM (16384 + 3 * ASTG)   // 65536 (attn path uses first 64KB)

__device__ __forceinline__ void attn_body(int h, int q0, char* smc)
{
    const uint32_t smb = s2u(smc);
    const int t = threadIdx.x, l = t & 31, wid = t >> 5;
    const size_t hb = (size_t)h * SEQ * HD;

    auto issue = [&](int ch) {
        const uint32_t kb = smb + 16384 + (ch % 3) * ASTG;
#pragma unroll
        for (int i = 0; i < 4; i++) {
            const int idx = t + i * 128, row = idx >> 3, s = idx & 7;
            const size_t g = hb + (size_t)(ch * 64 + row) * HD + s * 8;
            const uint32_t so = SWZ(row * 128 + s * 16);
            cpa16(kb + so,        g_k + g);
            cpa16(kb + 8192 + so, g_v + g);
        }
    };
#pragma unroll
    for (int i = 0; i < 8; i++) {
        const int idx = t + i * 128, row = idx >> 3, s = idx & 7;
        cpa16(smb + SWZ(row * 128 + s * 16),
              g_q + hb + (size_t)(q0 + row) * HD + s * 8);
    }
    issue(0); CPC();
    issue(1); CPC();

    float o[2][8][4];
#pragma unroll
    for (int mt = 0; mt < 2; mt++)
#pragma unroll
        for (int nt = 0; nt < 8; nt++)
#pragma unroll
            for (int j = 0; j < 4; j++) o[mt][nt][j] = 0.f;
    float csum[2][4];   // persistent row-sum accumulator (P @ ones)
#pragma unroll
    for (int mt = 0; mt < 2; mt++)
#pragma unroll
        for (int j = 0; j < 4; j++) csum[mt][j] = 0.f;
    uint32_t aq[4][2][4];

    const int ar8  = ((l >> 3) & 1) * 8 + (l & 7);
    const int ak16 = (l >> 4) * 16;
    const int br8  = ((l >> 4) & 1) * 8 + (l & 7);
    const int bk16 = ((l >> 3) & 1) * 16;
    const int vr8  = ((l >> 3) & 1) * 8 + (l & 7);
    const int vc16 = (l >> 4) * 16;

    for (int ch = 0; ch < 64; ch++) {
        CPW(1);
        __syncthreads();
        if (ch + 2 < 64) issue(ch + 2);
        CPC();

        if (ch == 0) {
#pragma unroll
            for (int ks = 0; ks < 4; ks++)
#pragma unroll
                for (int mt = 0; mt < 2; mt++)
                    ldsm4(aq[ks][mt],
                          smb + SWZ((wid * 32 + mt * 16 + ar8) * 128 + ks * 32 + ak16));
        }
        const uint32_t kbase = smb + 16384 + (ch % 3) * ASTG;
        const uint32_t vbase = kbase + 8192;

        // ---- S = Q @ K^T, fp16 accumulate (log2 units) ----
        uint32_t cs[2][8][2];
#pragma unroll
        for (int mt = 0; mt < 2; mt++)
#pragma unroll
            for (int nt = 0; nt < 8; nt++) { cs[mt][nt][0] = 0u; cs[mt][nt][1] = 0u; }
#pragma unroll
        for (int ks = 0; ks < 4; ks++) {
#pragma unroll
            for (int np = 0; np < 4; np++) {
                uint32_t b[4];
                ldsm4(b, kbase + SWZ((np * 16 + br8) * 128 + ks * 32 + bk16));
#pragma unroll
                for (int mt = 0; mt < 2; mt++) {
                    mma16816h(cs[mt][2*np],     aq[ks][mt], b[0], b[1]);
                    mma16816h(cs[mt][2*np + 1], aq[ks][mt], b[2], b[3]);
                }
            }
        }

        // ---- p = 2^s directly on packed f16 C regs (no cvt) ----
        uint32_t p01[2][8], p23[2][8];
#pragma unroll
        for (int mt = 0; mt < 2; mt++)
#pragma unroll
            for (int nt = 0; nt < 8; nt++) {
                p01[mt][nt] = h2exp2(cs[mt][nt][0]);
                p23[mt][nt] = h2exp2(cs[mt][nt][1]);
            }

        // ---- O += P @ V;  csum += P @ ones (row sums) ----
#pragma unroll
        for (int kt = 0; kt < 4; kt++) {
            uint32_t ap0[4] = { p01[0][2*kt], p23[0][2*kt],
                                p01[0][2*kt + 1], p23[0][2*kt + 1] };
            uint32_t ap1[4] = { p01[1][2*kt], p23[1][2*kt],
                                p01[1][2*kt + 1], p23[1][2*kt + 1] };
            mma16816(csum[0], ap0, ONESH2, ONESH2);
            mma16816(csum[1], ap1, ONESH2, ONESH2);
#pragma unroll
            for (int np = 0; np < 4; np++) {
                uint32_t b[4];
                ldsm4t(b, vbase + SWZ((kt * 16 + vr8) * 128 + np * 32 + vc16));
                mma16816(o[0][2*np],     ap0, b[0], b[1]);
                mma16816(o[0][2*np + 1], ap0, b[2], b[3]);
                mma16816(o[1][2*np],     ap1, b[0], b[1]);
                mma16816(o[1][2*np + 1], ap1, b[2], b[3]);
            }
        }
    }

    // normalize + store half [s][1024]; csum[mt][0]/[2] are complete row sums
#pragma unroll
    for (int mt = 0; mt < 2; mt++) {
        const float inv0 = 1.f / csum[mt][0];
        const float inv1 = 1.f / csum[mt][2];
        const int row = q0 + wid * 32 + mt * 16 + (l >> 2);
#pragma unroll
        for (int nt = 0; nt < 8; nt++) {
            const int col = h * 64 + nt * 8 + (l & 3) * 2;
            *(__half2*)(g_ao + (size_t)row * DM + col) =
                __floats2half2_rn(o[mt][nt][0] * inv0, o[mt][nt][1] * inv0);
            *(__half2*)(g_ao + (size_t)(row + 8) * DM + col) =
                __floats2half2_rn(o[mt][nt][2] * inv1, o[mt][nt][3] * inv1);
        }
    }
}

// ---------------- fused attention + out-projection --------------------------
// 1-D grid of 768. Blocks 0..511: attention tiles, q-block-major (h fastest)
// so whole q-blocks finish earliest. Blocks 512..767: out-GEMM tiles,
// m-block-major; each spins on its q-block's flag (16 attn producers), then
// runs the frozen gemm body. Out CTAs stream into the SM slots left idle by
// attention's partial second wave, hiding the out-GEMM inside the attn tail.
__global__ __launch_bounds__(128, 2) void attn_out(
    const float* __restrict__ bo, float* __restrict__ O32)
{
    extern __shared__ char smc[];
    const int bid = blockIdx.x;
    if (bid < SEQ/128 * NH) {                       // 512 attention tiles
        const int h = bid & (NH - 1);
        const int qb = bid >> 4;
        attn_body(h, qb * 128, smc);
        __threadfence();
        __syncthreads();
        if (threadIdx.x == 0) atomicAdd(&g_flags[qb], 1);
    } else {                                        // 256 out-GEMM tiles
        const int j = bid - SEQ/128 * NH;
        const int mb = j >> 3, n0 = (j & 7) * 128;
        if (threadIdx.x == 0) {
            while (atomicAdd(&g_flags[mb], 0) < NH) __nanosleep(128);
        }
        __syncthreads();
        __threadfence();
        gemm_body<1>(mb * 128, n0, 0, bo, nullptr, O32, smc);
    }
}

// ---------------------------------------------------------------------------
extern "C" void kernel_launch(void* const* d_in, const int* in_sizes, int n_in,
                              void* d_out, int out_size)
{
    const float* x  = (const float*)d_in[0];
    const float* wq = (const float*)d_in[1];
    const float* bq = (const float*)d_in[2];
    const float* wk = (const float*)d_in[3];
    const float* wv = (const float*)d_in[4];
    const float* bv = (const float*)d_in[5];
    const float* wo = (const float*)d_in[6];
    const float* bo = (const float*)d_in[7];
    float* out = (float*)d_out;

    cudaFuncSetAttribute(gemm_qkv, cudaFuncAttributeMaxDynamicSharedMemorySize, GEMM_SMEM);
    cudaFuncSetAttribute(attn_out, cudaFuncAttributeMaxDynamicSharedMemorySize, GEMM_SMEM);

    f2h_all<<<2048, 256>>>(x, wq, wk, wv, wo);

    gemm_qkv<<<dim3(DM / 128, SEQ / 128, 3), 128, GEMM_SMEM>>>(bq, bv);

    attn_out<<<SEQ/128 * NH + (SEQ/128) * (DM/128), 128, GEMM_SMEM>>>(bo, out);
}

// round 16
// speedup vs baseline: 1.0433x; 1.0433x over previous
#include <cuda_runtime.h>
#include <cuda_fp16.h>
#include <cstdint>

#define SEQ 4096
#define DM  1024
#define NH  16
#define HD  64
#define QSCALE 0.1803368801111204f   // 0.125 * log2(e): S comes out in log2 units
#define ONESH2 0x3C003C00u           // half2(1.0, 1.0)

// ---------------- scratch (__device__ globals; no allocs allowed) -----------
__device__ __half g_xh[SEQ*DM];
__device__ __half g_wqh[DM*DM], g_wkh[DM*DM], g_wvh[DM*DM], g_woh[DM*DM];
__device__ __half g_q[SEQ*DM], g_k[SEQ*DM], g_v[SEQ*DM];   // [h][s][64]
__device__ __half g_ao[SEQ*DM];                             // [s][1024]

// ---------------- PTX helpers ----------------------------------------------
#define SWZ(o) ((uint32_t)(o) ^ (((uint32_t)(o) >> 3) & 0x70u))

__device__ __forceinline__ uint32_t s2u(const void* p) {
    uint32_t a;
    asm("{ .reg .u64 t; cvta.to.shared.u64 t, %1; cvt.u32.u64 %0, t; }"
        : "=r"(a) : "l"(p));
    return a;
}
__device__ __forceinline__ void cpa16(uint32_t s, const void* g) {
    asm volatile("cp.async.cg.shared.global [%0], [%1], 16;" :: "r"(s), "l"(g));
}
#define CPC()  asm volatile("cp.async.commit_group;" ::: "memory")
#define CPW(n) asm volatile("cp.async.wait_group %0;" :: "n"(n) : "memory")

__device__ __forceinline__ void ldsm4(uint32_t* r, uint32_t a) {
    asm volatile("ldmatrix.sync.aligned.m8n8.x4.shared.b16 {%0,%1,%2,%3}, [%4];"
                 : "=r"(r[0]), "=r"(r[1]), "=r"(r[2]), "=r"(r[3]) : "r"(a));
}
__device__ __forceinline__ void ldsm4t(uint32_t* r, uint32_t a) {
    asm volatile("ldmatrix.sync.aligned.m8n8.x4.trans.shared.b16 {%0,%1,%2,%3}, [%4];"
                 : "=r"(r[0]), "=r"(r[1]), "=r"(r[2]), "=r"(r[3]) : "r"(a));
}
__device__ __forceinline__ void mma16816(float* c, const uint32_t* a,
                                         uint32_t b0, uint32_t b1) {
    asm volatile(
        "mma.sync.aligned.m16n8k16.row.col.f32.f16.f16.f32 "
        "{%0,%1,%2,%3},{%4,%5,%6,%7},{%8,%9},{%0,%1,%2,%3};"
        : "+f"(c[0]), "+f"(c[1]), "+f"(c[2]), "+f"(c[3])
        : "r"(a[0]), "r"(a[1]), "r"(a[2]), "r"(a[3]), "r"(b0), "r"(b1));
}
// fp16-accumulator variant: C regs pack {row r: c,c+1} / {row r+8: c,c+1}
__device__ __forceinline__ void mma16816h(uint32_t* c, const uint32_t* a,
                                          uint32_t b0, uint32_t b1) {
    asm volatile(
        "mma.sync.aligned.m16n8k16.row.col.f16.f16.f16.f16 "
        "{%0,%1},{%2,%3,%4,%5},{%6,%7},{%0,%1};"
        : "+r"(c[0]), "+r"(c[1])
        : "r"(a[0]), "r"(a[1]), "r"(a[2]), "r"(a[3]), "r"(b0), "r"(b1));
}
__device__ __forceinline__ uint32_t h2exp2(uint32_t x) {
    uint32_t r;
    asm("ex2.approx.f16x2 %0, %1;" : "=r"(r) : "r"(x));
    return r;
}

// ---------------- fp32 -> fp16 convert: block-static segmentation -----------
// 2048 blocks x 256 threads. Blocks 0..1023: x (1M float4). Then 4 bands of
// 256 blocks: wq/wk/wv/wo (256K float4 each). Each block converts a
// contiguous 1024-float4 slice in 4 unrolled coalesced iterations (MLP=4,
// no per-iteration branching) — fixes the 38%-of-DRAM ceiling R13 measured.
__global__ void f2h_all(const float* __restrict__ x,  const float* __restrict__ wq,
                        const float* __restrict__ wk, const float* __restrict__ wv,
                        const float* __restrict__ wo)
{
    const int b = blockIdx.x;
    const float4* s;
    __half2* d;
    int base;
    if (b < 1024) {
        s = (const float4*)x; d = (__half2*)g_xh; base = b << 10;
    } else {
        const int j = b - 1024, seg = j >> 8;
        base = (j & 255) << 10;
        if      (seg == 0) { s = (const float4*)wq; d = (__half2*)g_wqh; }
        else if (seg == 1) { s = (const float4*)wk; d = (__half2*)g_wkh; }
        else if (seg == 2) { s = (const float4*)wv; d = (__half2*)g_wvh; }
        else               { s = (const float4*)wo; d = (__half2*)g_woh; }
    }
#pragma unroll
    for (int it = 0; it < 4; it++) {
        const int off = base + it * 256 + threadIdx.x;
        const float4 v = s[off];
        d[2 * off]     = __floats2half2_rn(v.x, v.y);
        d[2 * off + 1] = __floats2half2_rn(v.z, v.w);
    }
}

// ---------------- GEMM: CTA 128x128, 4 warps (2x2), warp 64x64 --------------
// BK=64, 3-stage cp.async (.cg), SW128. Benched at its mma.sync pipe floor
// (30.8us, tensor 51%) across six rounds. Frozen.
#define GSTG 32768
#define GEMM_SMEM (3 * GSTG)    // 98304

template <int IS_OUT>
__global__ __launch_bounds__(128, 2) void gemm_h(
    const float* __restrict__ bqv, const float* __restrict__ bvv,
    float* __restrict__ O32)
{
    extern __shared__ char smc[];
    const uint32_t smb = s2u(smc);
    const int t = threadIdx.x, l = t & 31, wid = t >> 5;
    const int wm = wid >> 1, wn = wid & 1;
    const int m0 = blockIdx.y * 128, n0 = blockIdx.x * 128, z = blockIdx.z;

    const __half* A = IS_OUT ? g_ao : g_xh;
    const __half* B = IS_OUT ? g_woh
                             : (z == 0) ? g_wqh : (z == 1) ? g_wkh : g_wvh;

    float c[4][8][4];
#pragma unroll
    for (int mt = 0; mt < 4; mt++)
#pragma unroll
        for (int nt = 0; nt < 8; nt++)
#pragma unroll
            for (int j = 0; j < 4; j++) c[mt][nt][j] = 0.f;

    auto issue = [&](int ch) {
        const uint32_t sa = smb + (ch % 3) * GSTG;
#pragma unroll
        for (int i = 0; i < 8; i++) {
            const int idx = t + i * 128, row = idx >> 3, s = idx & 7;
            const size_t ko = (size_t)ch * 64 + s * 8;
            const uint32_t so = SWZ(row * 128 + s * 16);
            cpa16(sa + so,         A + (size_t)(m0 + row) * DM + ko);
            cpa16(sa + 16384 + so, B + (size_t)(n0 + row) * DM + ko);
        }
    };
    issue(0); CPC();
    issue(1); CPC();

    const int ar8  = ((l >> 3) & 1) * 8 + (l & 7);
    const int ak16 = (l >> 4) * 16;
    const int br8  = ((l >> 4) & 1) * 8 + (l & 7);
    const int bk16 = ((l >> 3) & 1) * 16;

    for (int ch = 0; ch < 16; ch++) {
        CPW(1);
        __syncthreads();

        const uint32_t sa = smb + (ch % 3) * GSTG, sb = sa + 16384;
#pragma unroll
        for (int ks = 0; ks < 4; ks++) {
            uint32_t a[4][4], b[4][4];
#pragma unroll
            for (int mt = 0; mt < 4; mt++)
                ldsm4(a[mt], sa + SWZ((wm * 64 + mt * 16 + ar8) * 128 + ks * 32 + ak16));
#pragma unroll
            for (int np = 0; np < 4; np++)
                ldsm4(b[np], sb + SWZ((wn * 64 + np * 16 + br8) * 128 + ks * 32 + bk16));
#pragma unroll
            for (int mt = 0; mt < 4; mt++)
#pragma unroll
                for (int np = 0; np < 4; np++) {
                    mma16816(c[mt][2*np],     a[mt], b[np][0], b[np][1]);
                    mma16816(c[mt][2*np + 1], a[mt], b[np][2], b[np][3]);
                }
            if (ks == 0 && ch + 2 < 16) { issue(ch + 2); CPC(); }
        }
    }

    // epilogue
    const float scale = (!IS_OUT && z == 0) ? QSCALE : 1.f;
    const float* bias = IS_OUT ? bqv : (z == 2) ? bvv : bqv;
    const int hasb = IS_OUT || (z != 1);
#pragma unroll
    for (int mt = 0; mt < 4; mt++) {
        const int r = m0 + wm * 64 + mt * 16 + (l >> 2);
#pragma unroll
        for (int nt = 0; nt < 8; nt++) {
            const int n = n0 + wn * 64 + nt * 8 + (l & 3) * 2;
            const float b0 = hasb ? bias[n] : 0.f;
            const float b1 = hasb ? bias[n + 1] : 0.f;
            if (IS_OUT) {
                *(float2*)(O32 + (size_t)r * DM + n) =
                    make_float2(c[mt][nt][0] + b0, c[mt][nt][1] + b1);
                *(float2*)(O32 + (size_t)(r + 8) * DM + n) =
                    make_float2(c[mt][nt][2] + b0, c[mt][nt][3] + b1);
            } else {
                __half* Oh = (z == 0) ? g_q : (z == 1) ? g_k : g_v;
                const int hh = n >> 6, hd = n & 63;
                *(__half2*)(Oh + ((size_t)hh * SEQ + r) * HD + hd) =
                    __floats2half2_rn((c[mt][nt][0] + b0) * scale,
                                      (c[mt][nt][1] + b1) * scale);
                *(__half2*)(Oh + ((size_t)hh * SEQ + r + 8) * HD + hd) =
                    __floats2half2_rn((c[mt][nt][2] + b0) * scale,
                                      (c[mt][nt][3] + b1) * scale);
            }
        }
    }
}

// ---------------- attention: exact R9/R12 champion (286.7us) ----------------
// CTA = (128 q, head), 4 warps, warp 32q x 64 keys, 64-key chunks, 3-stage.
// fp16-acc S-MMA feeds ex2 directly; row sums via ones-MMA. R10/R11/R13 all
// proved any perturbation of this kernel or its launch context regresses.
#define ASTG 16384
#define ATTN_SMEM (16384 + 3 * ASTG)   // 65536

__global__ __launch_bounds__(128, 2) void attn_h()
{
    extern __shared__ char smc[];
    const uint32_t smb = s2u(smc);
    const int t = threadIdx.x, l = t & 31, wid = t >> 5;
    const int h = blockIdx.y, q0 = blockIdx.x * 128;
    const size_t hb = (size_t)h * SEQ * HD;

    auto issue = [&](int ch) {
        const uint32_t kb = smb + 16384 + (ch % 3) * ASTG;
#pragma unroll
        for (int i = 0; i < 4; i++) {
            const int idx = t + i * 128, row = idx >> 3, s = idx & 7;
            const size_t g = hb + (size_t)(ch * 64 + row) * HD + s * 8;
            const uint32_t so = SWZ(row * 128 + s * 16);
            cpa16(kb + so,        g_k + g);
            cpa16(kb + 8192 + so, g_v + g);
        }
    };
#pragma unroll
    for (int i = 0; i < 8; i++) {
        const int idx = t + i * 128, row = idx >> 3, s = idx & 7;
        cpa16(smb + SWZ(row * 128 + s * 16),
              g_q + hb + (size_t)(q0 + row) * HD + s * 8);
    }
    issue(0); CPC();
    issue(1); CPC();

    float o[2][8][4];
#pragma unroll
    for (int mt = 0; mt < 2; mt++)
#pragma unroll
        for (int nt = 0; nt < 8; nt++)
#pragma unroll
            for (int j = 0; j < 4; j++) o[mt][nt][j] = 0.f;
    float csum[2][4];   // persistent row-sum accumulator (P @ ones)
#pragma unroll
    for (int mt = 0; mt < 2; mt++)
#pragma unroll
        for (int j = 0; j < 4; j++) csum[mt][j] = 0.f;
    uint32_t aq[4][2][4];

    const int ar8  = ((l >> 3) & 1) * 8 + (l & 7);
    const int ak16 = (l >> 4) * 16;
    const int br8  = ((l >> 4) & 1) * 8 + (l & 7);
    const int bk16 = ((l >> 3) & 1) * 16;
    const int vr8  = ((l >> 3) & 1) * 8 + (l & 7);
    const int vc16 = (l >> 4) * 16;

    for (int ch = 0; ch < 64; ch++) {
        CPW(1);
        __syncthreads();
        if (ch + 2 < 64) issue(ch + 2);
        CPC();

        if (ch == 0) {
#pragma unroll
            for (int ks = 0; ks < 4; ks++)
#pragma unroll
                for (int mt = 0; mt < 2; mt++)
                    ldsm4(aq[ks][mt],
                          smb + SWZ((wid * 32 + mt * 16 + ar8) * 128 + ks * 32 + ak16));
        }
        const uint32_t kbase = smb + 16384 + (ch % 3) * ASTG;
        const uint32_t vbase = kbase + 8192;

        // ---- S = Q @ K^T, fp16 accumulate (log2 units) ----
        uint32_t cs[2][8][2];
#pragma unroll
        for (int mt = 0; mt < 2; mt++)
#pragma unroll
            for (int nt = 0; nt < 8; nt++) { cs[mt][nt][0] = 0u; cs[mt][nt][1] = 0u; }
#pragma unroll
        for (int ks = 0; ks < 4; ks++) {
#pragma unroll
            for (int np = 0; np < 4; np++) {
                uint32_t b[4];
                ldsm4(b, kbase + SWZ((np * 16 + br8) * 128 + ks * 32 + bk16));
#pragma unroll
                for (int mt = 0; mt < 2; mt++) {
                    mma16816h(cs[mt][2*np],     aq[ks][mt], b[0], b[1]);
                    mma16816h(cs[mt][2*np + 1], aq[ks][mt], b[2], b[3]);
                }
            }
        }

        // ---- p = 2^s directly on packed f16 C regs (no cvt) ----
        uint32_t p01[2][8], p23[2][8];
#pragma unroll
        for (int mt = 0; mt < 2; mt++)
#pragma unroll
            for (int nt = 0; nt < 8; nt++) {
                p01[mt][nt] = h2exp2(cs[mt][nt][0]);
                p23[mt][nt] = h2exp2(cs[mt][nt][1]);
            }

        // ---- O += P @ V;  csum += P @ ones (row sums) ----
#pragma unroll
        for (int kt = 0; kt < 4; kt++) {
            uint32_t ap0[4] = { p01[0][2*kt], p23[0][2*kt],
                                p01[0][2*kt + 1], p23[0][2*kt + 1] };
            uint32_t ap1[4] = { p01[1][2*kt], p23[1][2*kt],
                                p01[1][2*kt + 1], p23[1][2*kt + 1] };
            mma16816(csum[0], ap0, ONESH2, ONESH2);
            mma16816(csum[1], ap1, ONESH2, ONESH2);
#pragma unroll
            for (int np = 0; np < 4; np++) {
                uint32_t b[4];
                ldsm4t(b, vbase + SWZ((kt * 16 + vr8) * 128 + np * 32 + vc16));
                mma16816(o[0][2*np],     ap0, b[0], b[1]);
                mma16816(o[0][2*np + 1], ap0, b[2], b[3]);
                mma16816(o[1][2*np],     ap1, b[0], b[1]);
                mma16816(o[1][2*np + 1], ap1, b[2], b[3]);
            }
        }
    }

    // normalize + store half [s][1024]; csum[mt][0]/[2] are complete row sums
#pragma unroll
    for (int mt = 0; mt < 2; mt++) {
        const float inv0 = 1.f / csum[mt][0];
        const float inv1 = 1.f / csum[mt][2];
        const int row = q0 + wid * 32 + mt * 16 + (l >> 2);
#pragma unroll
        for (int nt = 0; nt < 8; nt++) {
            const int col = h * 64 + nt * 8 + (l & 3) * 2;
            *(__half2*)(g_ao + (size_t)row * DM + col) =
                __floats2half2_rn(o[mt][nt][0] * inv0, o[mt][nt][1] * inv0);
            *(__half2*)(g_ao + (size_t)(row + 8) * DM + col) =
                __floats2half2_rn(o[mt][nt][2] * inv1, o[mt][nt][3] * inv1);
        }
    }
}

// ---------------------------------------------------------------------------
extern "C" void kernel_launch(void* const* d_in, const int* in_sizes, int n_in,
                              void* d_out, int out_size)
{
    const float* x  = (const float*)d_in[0];
    const float* wq = (const float*)d_in[1];
    const float* bq = (const float*)d_in[2];
    const float* wk = (const float*)d_in[3];
    const float* wv = (const float*)d_in[4];
    const float* bv = (const float*)d_in[5];
    const float* wo = (const float*)d_in[6];
    const float* bo = (const float*)d_in[7];
    float* out = (float*)d_out;

    cudaFuncSetAttribute(gemm_h<0>, cudaFuncAttributeMaxDynamicSharedMemorySize, GEMM_SMEM);
    cudaFuncSetAttribute(gemm_h<1>, cudaFuncAttributeMaxDynamicSharedMemorySize, GEMM_SMEM);
    cudaFuncSetAttribute(attn_h,    cudaFuncAttributeMaxDynamicSharedMemorySize, ATTN_SMEM);

    f2h_all<<<2048, 256>>>(x, wq, wk, wv, wo);

    gemm_h<0><<<dim3(DM / 128, SEQ / 128, 3), 128, GEMM_SMEM>>>(bq, bv, nullptr);

    attn_h<<<dim3(SEQ / 128, NH), 128, ATTN_SMEM>>>();

    gemm_h<1><<<dim3(DM / 128, SEQ / 128, 1), 128, GEMM_SMEM>>>(bo, nullptr, out);
}